// round 11
// baseline (speedup 1.0000x reference)
#include <cuda_runtime.h>

// B=16, Wn=64, K=256, E=128, O=64

typedef unsigned long long ull;

__device__ __forceinline__ ull f2_add(ull a, ull b) {
    ull r; asm("add.rn.f32x2 %0,%1,%2;" : "=l"(r) : "l"(a), "l"(b)); return r;
}
__device__ __forceinline__ ull f2_fma(ull a, ull b, ull c) {
    ull r; asm("fma.rn.f32x2 %0,%1,%2,%3;" : "=l"(r) : "l"(a), "l"(b), "l"(c)); return r;
}
__device__ __forceinline__ float f2_hadd(ull a) {
    float lo, hi; asm("mov.b64 {%0,%1},%2;" : "=f"(lo), "=f"(hi) : "l"(a)); return lo + hi;
}
__device__ __forceinline__ ull f2_dup(float v) {
    ull r; asm("mov.b64 %0,{%1,%1};" : "=l"(r) : "f"(v)); return r;
}
__device__ __forceinline__ void f2_unpack(ull a, float& lo, float& hi) {
    asm("mov.b64 {%0,%1},%2;" : "=f"(lo), "=f"(hi) : "l"(a));
}

// Scratch
__device__ float g_L[16 * 256 * 128];
__device__ float g_R[16 * 256 * 128];
__device__ float g_sL[16 * 256];
__device__ float g_sR[16 * 256];
__device__ float g_h[16 * 256 * 64];

// ---------------------------------------------------------------------------
// k1: C[4096,256] = A[4096,64] x W[256,64]^T ; 2m x 4n register tiles,
// fused sL/sR row-dots (scale 0.6). grid = 512 (m-tile 32), 256 threads.
// ---------------------------------------------------------------------------
__global__ void __launch_bounds__(256, 4)
k1_lr(const float* __restrict__ x, const float* __restrict__ lin_w,
      const float* __restrict__ lin_b, const float* __restrict__ a) {
    __shared__ float As[64 * 36];   // As[w][m], m = 0..31
    __shared__ float Ws[64 * 68];   // Ws[w][n], n = 0..63

    int bx = blockIdx.x;
    int mt = bx >> 2, nt = bx & 3;
    int b = mt >> 3, k0 = (mt & 7) * 32;
    int half = nt >> 1, e0 = (nt & 1) * 64;
    int tid = threadIdx.x;

    // stage x tile (32 k-rows x 64 w): 512 float4, 2 per thread
#pragma unroll
    for (int t = 0; t < 2; t++) {
        int idx = t * 256 + tid;
        int w = idx >> 3, kk4 = idx & 7;
        float4 v = *reinterpret_cast<const float4*>(x + b * 16384 + w * 256 + k0 + kk4 * 4);
        *reinterpret_cast<float4*>(&As[w * 36 + kk4 * 4]) = v;
    }
    // stage weights transposed: 1024 float4, 4 per thread
#pragma unroll
    for (int t = 0; t < 4; t++) {
        int idx = t * 256 + tid;
        int n = idx >> 4, w4 = idx & 15;
        float4 v = *reinterpret_cast<const float4*>(lin_w + (e0 + n) * 128 + half * 64 + w4 * 4);
        Ws[(w4 * 4 + 0) * 68 + n] = v.x;
        Ws[(w4 * 4 + 1) * 68 + n] = v.y;
        Ws[(w4 * 4 + 2) * 68 + n] = v.z;
        Ws[(w4 * 4 + 3) * 68 + n] = v.w;
    }
    __syncthreads();

    int mg = tid >> 4, ng = tid & 15;   // m = k0 + mg*2 (+1), n = e0 + ng*4..
    ull acc[4] = {0ULL, 0ULL, 0ULL, 0ULL};

#pragma unroll 8
    for (int w = 0; w < 64; w++) {
        ull a0 = *reinterpret_cast<const ull*>(&As[w * 36 + mg * 2]);
        float4 wn = *reinterpret_cast<const float4*>(&Ws[w * 68 + ng * 4]);
        acc[0] = f2_fma(a0, f2_dup(wn.x), acc[0]);
        acc[1] = f2_fma(a0, f2_dup(wn.y), acc[1]);
        acc[2] = f2_fma(a0, f2_dup(wn.z), acc[2]);
        acc[3] = f2_fma(a0, f2_dup(wn.w), acc[3]);
    }

    float4 lb4 = make_float4(0.f, 0.f, 0.f, 0.f);
    if (half == 0) lb4 = *reinterpret_cast<const float4*>(lin_b + e0 + ng * 4);
    float4 a6 = *reinterpret_cast<const float4*>(a + e0 + ng * 4);
    a6.x *= 0.6f; a6.y *= 0.6f; a6.z *= 0.6f; a6.w *= 0.6f;

    float lo[4], hi[4];
#pragma unroll
    for (int n = 0; n < 4; n++) f2_unpack(acc[n], lo[n], hi[n]);
    float l0 = lo[0] + lb4.x, l1 = lo[1] + lb4.y, l2 = lo[2] + lb4.z, l3 = lo[3] + lb4.w;
    float h0 = hi[0] + lb4.x, h1 = hi[1] + lb4.y, h2 = hi[2] + lb4.z, h3 = hi[3] + lb4.w;

    float* outbase = (half ? g_R : g_L) + (b * 256 + k0 + mg * 2) * 128 + e0 + ng * 4;
    *reinterpret_cast<float4*>(outbase) = make_float4(l0, l1, l2, l3);
    *reinterpret_cast<float4*>(outbase + 128) = make_float4(h0, h1, h2, h3);

    float part[2];
    part[0] = l0 * a6.x + l1 * a6.y + l2 * a6.z + l3 * a6.w;
    part[1] = h0 * a6.x + h1 * a6.y + h2 * a6.z + h3 * a6.w;
#pragma unroll
    for (int o = 8; o > 0; o >>= 1) {
        part[0] += __shfl_down_sync(0xffffffffu, part[0], o, 16);
        part[1] += __shfl_down_sync(0xffffffffu, part[1], o, 16);
    }
    if (ng == 0) {
        float* sp = (half ? g_sR : g_sL) + b * 256 + k0 + mg * 2;
        atomicAdd(sp, part[0]);
        atomicAdd(sp + 1, part[1]);
    }
}

// ---------------------------------------------------------------------------
// k2: e = sL+sR + sum(0.4a)|L+R| + bias; softmax; h = sigmoid(p @ v).
// grid = 128 (16b x 8 itiles of 32), 256 thr.
// e-phase: 4 ig x 16 jg x 4 eh; 8i x 4j tiles; double-buffered R (1 sync/stage).
// smem 218,368 B.
// ---------------------------------------------------------------------------
__global__ void __launch_bounds__(256, 1)
k2_attn(const float* __restrict__ x, const float* __restrict__ bias_kk,
        const float* __restrict__ a) {
    extern __shared__ float S[];
    const int LS = 0;        // 32 x 132
    const int RS0 = 4224;    // 64 x 130
    const int RS1 = 12544;   // 64 x 130
    const int E0 = 20864;    // 32 x 260  -> probabilities after softmax
    const int E1 = 29184;    // 32 x 260  -> xs j-half 0 after softmax
    const int E2 = 37504;    // 32 x 260  -> xs j-half 1 after softmax
    const int E3 = 45824;    // 32 x 260
    const int CS = 54144;    // 128 (0.4*a)
    const int SRS = 54272;   // 256
    const int SLS = 54528;   // 32
    const int INVS = 54560;  // 32   (total 54592 floats = 218,368 B)
    const ull ABSM = 0x7FFFFFFF7FFFFFFFULL;

    int tid = threadIdx.x;
    int b = blockIdx.x >> 3;
    int i0 = (blockIdx.x & 7) << 5;

    const float* Lg = g_L + (b * 256 + i0) * 128;
#pragma unroll
    for (int t = 0; t < 4; t++) {
        int idx = t * 256 + tid;
        int row = idx >> 5, c4 = idx & 31;
        float4 v = *reinterpret_cast<const float4*>(Lg + row * 128 + c4 * 4);
        *reinterpret_cast<float4*>(&S[LS + row * 132 + c4 * 4]) = v;
    }
    if (tid < 128) S[CS + tid] = 0.4f * a[tid];
    S[SRS + tid] = g_sR[b * 256 + tid];
    if (tid < 32) S[SLS + tid] = g_sL[b * 256 + i0 + tid];

    int eh = tid >> 6;          // e-quarter 0..3
    int r = tid & 63;
    int ig = r >> 4;            // 0..3 -> rows ig + 4u
    int jg = r & 15;            // 0..15 -> cols jt*64 + jg + 16v
    const ull* Lp[8];
#pragma unroll
    for (int u = 0; u < 8; u++)
        Lp[u] = reinterpret_cast<const ull*>(&S[LS + (ig + 4 * u) * 132]) + eh * 16;
    const ull* Cp = reinterpret_cast<const ull*>(&S[CS]) + eh * 16;
    float* Eq = &S[E0 + eh * 8320];

    // prologue: stage0 -> RS0; prefetch stage1 into pf
    const float* Rgb = g_R + (b * 256) * 128;
    float4 pf[8];
#pragma unroll
    for (int t = 0; t < 8; t++) {
        int idx = t * 256 + tid;
        int row = idx >> 5, c4 = idx & 31;
        pf[t] = *reinterpret_cast<const float4*>(Rgb + row * 128 + c4 * 4);
    }
#pragma unroll
    for (int t = 0; t < 8; t++) {
        int idx = t * 256 + tid;
        int row = idx >> 5, c4 = idx & 31;
        float* d = &S[RS0 + row * 130 + c4 * 4];
        *reinterpret_cast<float2*>(d) = make_float2(pf[t].x, pf[t].y);
        *reinterpret_cast<float2*>(d + 2) = make_float2(pf[t].z, pf[t].w);
    }
#pragma unroll
    for (int t = 0; t < 8; t++) {
        int idx = t * 256 + tid;
        int row = idx >> 5, c4 = idx & 31;
        pf[t] = *reinterpret_cast<const float4*>(Rgb + 64 * 128 + row * 128 + c4 * 4);
    }
    __syncthreads();

    for (int jt = 0; jt < 4; jt++) {
        int Rb = (jt & 1) ? RS1 : RS0;
        const ull* Rp0 = reinterpret_cast<const ull*>(&S[Rb + (jg) * 130]) + eh * 16;
        const ull* Rp1 = reinterpret_cast<const ull*>(&S[Rb + (jg + 16) * 130]) + eh * 16;
        const ull* Rp2 = reinterpret_cast<const ull*>(&S[Rb + (jg + 32) * 130]) + eh * 16;
        const ull* Rp3 = reinterpret_cast<const ull*>(&S[Rb + (jg + 48) * 130]) + eh * 16;

        ull acc[8][4];
#pragma unroll
        for (int u = 0; u < 8; u++)
#pragma unroll
            for (int v = 0; v < 4; v++) acc[u][v] = 0ULL;

#pragma unroll 2
        for (int ep = 0; ep < 16; ep++) {
            ull c = Cp[ep];
            ull r0 = Rp0[ep], r1 = Rp1[ep], r2 = Rp2[ep], r3 = Rp3[ep];
#pragma unroll
            for (int u = 0; u < 8; u++) {
                ull l = Lp[u][ep];
                acc[u][0] = f2_fma(f2_add(l, r0) & ABSM, c, acc[u][0]);
                acc[u][1] = f2_fma(f2_add(l, r1) & ABSM, c, acc[u][1]);
                acc[u][2] = f2_fma(f2_add(l, r2) & ABSM, c, acc[u][2]);
                acc[u][3] = f2_fma(f2_add(l, r3) & ABSM, c, acc[u][3]);
            }
        }
#pragma unroll
        for (int u = 0; u < 8; u++) {
            int i = ig + 4 * u;
#pragma unroll
            for (int v = 0; v < 4; v++) {
                int j = jt * 64 + jg + 16 * v;
                Eq[i * 260 + j] = f2_hadd(acc[u][v]);
            }
        }

        // stage jt+1 (held in pf) into the other buffer; prefetch jt+2
        if (jt < 3) {
            int Rn = ((jt + 1) & 1) ? RS1 : RS0;
#pragma unroll
            for (int t = 0; t < 8; t++) {
                int idx = t * 256 + tid;
                int row = idx >> 5, c4 = idx & 31;
                float* d = &S[Rn + row * 130 + c4 * 4];
                *reinterpret_cast<float2*>(d) = make_float2(pf[t].x, pf[t].y);
                *reinterpret_cast<float2*>(d + 2) = make_float2(pf[t].z, pf[t].w);
            }
        }
        if (jt < 2) {
            const float* Rgn = Rgb + (jt + 2) * 64 * 128;
#pragma unroll
            for (int t = 0; t < 8; t++) {
                int idx = t * 256 + tid;
                int row = idx >> 5, c4 = idx & 31;
                pf[t] = *reinterpret_cast<const float4*>(Rgn + row * 128 + c4 * 4);
            }
        }
        __syncthreads();
    }

    // softmax over j: 8 warps x 4 rows; fold 4 e-quarters + linear terms
    int wid = tid >> 5, lane = tid & 31;
#pragma unroll
    for (int s = 0; s < 4; s++) {
        int rr = wid * 4 + s;
        float sl = S[SLS + rr];
        const float* bp = bias_kk + (i0 + rr) * 256;
        float v[8];
        float m = -1e30f;
#pragma unroll
        for (int u = 0; u < 8; u++) {
            int c = u * 32 + lane;
            int o = rr * 260 + c;
            v[u] = S[E0 + o] + S[E1 + o] + S[E2 + o] + S[E3 + o]
                 + sl + S[SRS + c] + bp[c];
            m = fmaxf(m, v[u]);
        }
#pragma unroll
        for (int o = 16; o > 0; o >>= 1) m = fmaxf(m, __shfl_xor_sync(0xffffffffu, m, o));
        float sum = 0.f;
#pragma unroll
        for (int u = 0; u < 8; u++) {
            float p = __expf(v[u] - m);
            S[E0 + rr * 260 + u * 32 + lane] = p;
            sum += p;
        }
#pragma unroll
        for (int o = 16; o > 0; o >>= 1) sum += __shfl_xor_sync(0xffffffffu, sum, o);
        if (lane == 0) S[INVS + rr] = 1.f / sum;
    }
    __syncthreads();

    // stage x tile: j-half 0 -> E1, j-half 1 -> E2 (coalesced float4 LDG)
#pragma unroll
    for (int t = 0; t < 16; t++) {
        int idx = t * 256 + tid;
        int w2 = idx >> 6, jc4 = idx & 63;
        float4 v = *reinterpret_cast<const float4*>(x + b * 16384 + w2 * 256 + jc4 * 4);
        int base = (jc4 < 32) ? E1 : E2;
        float* d = &S[base + w2 * 130 + (jc4 & 31) * 4];
        *reinterpret_cast<float2*>(d) = make_float2(v.x, v.y);
        *reinterpret_cast<float2*>(d + 2) = make_float2(v.z, v.w);
    }
    __syncthreads();

    // h: thread = (w in 64, ih = i-quarter of 8); f[8] over full j
    int w = tid & 63;
    int ih = tid >> 6;
    ull f[8];
#pragma unroll
    for (int ii = 0; ii < 8; ii++) f[ii] = 0ULL;
    const float* pb = &S[E0 + (ih * 8) * 260];
    const ull* xq0 = reinterpret_cast<const ull*>(&S[E1 + w * 130]);
    const ull* xq1 = reinterpret_cast<const ull*>(&S[E2 + w * 130]);
    for (int j4 = 0; j4 < 32; j4++) {
        ull x0 = xq0[j4 * 2], x1 = xq0[j4 * 2 + 1];
#pragma unroll
        for (int ii = 0; ii < 8; ii++) {
            ulonglong2 pq = *reinterpret_cast<const ulonglong2*>(pb + ii * 260 + j4 * 4);
            f[ii] = f2_fma(x0, pq.x, f[ii]);
            f[ii] = f2_fma(x1, pq.y, f[ii]);
        }
    }
    for (int j4 = 0; j4 < 32; j4++) {
        ull x0 = xq1[j4 * 2], x1 = xq1[j4 * 2 + 1];
#pragma unroll
        for (int ii = 0; ii < 8; ii++) {
            ulonglong2 pq = *reinterpret_cast<const ulonglong2*>(pb + ii * 260 + 128 + j4 * 4);
            f[ii] = f2_fma(x0, pq.x, f[ii]);
            f[ii] = f2_fma(x1, pq.y, f[ii]);
        }
    }
#pragma unroll
    for (int ii = 0; ii < 8; ii++) {
        int i = ih * 8 + ii;
        float val = f2_hadd(f[ii]) * S[INVS + i];
        g_h[(b * 256 + i0 + i) * 64 + w] = 1.f / (1.f + __expf(-val));
    }
}

// ---------------------------------------------------------------------------
// k3: out[b,w,o] = sum_k h[b,k,w] fc_w[o,k] + fc_b[o]
// grid = 256 (16b x 8 wtiles x 2 ohalves), 256 thr, single staging + 1 sync
// ---------------------------------------------------------------------------
__global__ void __launch_bounds__(256, 4)
k3_fc(const float* __restrict__ fc_w, const float* __restrict__ fc_b,
      float* __restrict__ out) {
    __shared__ float T[32 * 258 + 8 * 258];
    const int FW = 0;          // 32 x 258
    const int HS = 32 * 258;   // 8 x 258

    int bx = blockIdx.x;
    int b = bx >> 4;
    int rem = bx & 15;
    int wq = rem >> 1, oh = rem & 1;
    int w0 = wq * 8, o0 = oh * 32;
    int tid = threadIdx.x;
    int w8 = tid & 7, og = tid >> 3;   // og 0..31

    // stage fc_w rows o0..o0+31: 2048 float4, 8 per thread
#pragma unroll
    for (int t = 0; t < 8; t++) {
        int idx = t * 256 + tid;
        int row = idx >> 6, c4 = idx & 63;
        float4 v = *reinterpret_cast<const float4*>(fc_w + (o0 + row) * 256 + c4 * 4);
        float* d = &T[FW + row * 258 + c4 * 4];
        *reinterpret_cast<float2*>(d) = make_float2(v.x, v.y);
        *reinterpret_cast<float2*>(d + 2) = make_float2(v.z, v.w);
    }
    // stage h: 2048 scalars, 8 per thread
#pragma unroll
    for (int t = 0; t < 8; t++) {
        int idx = t * 256 + tid;
        int kk = idx >> 3, ww = idx & 7;
        T[HS + ww * 258 + kk] = g_h[(b * 256 + kk) * 64 + w0 + ww];
    }
    __syncthreads();

    const ull* hp = reinterpret_cast<const ull*>(&T[HS + w8 * 258]);
    const ull* f0 = reinterpret_cast<const ull*>(&T[FW + og * 258]);
    ull acc = 0ULL;
#pragma unroll 16
    for (int kp = 0; kp < 128; kp++)
        acc = f2_fma(hp[kp], f0[kp], acc);

    out[(b * 64 + w0 + w8) * 64 + o0 + og] = f2_hadd(acc) + fc_b[o0 + og];
}

// ---------------------------------------------------------------------------
extern "C" void kernel_launch(void* const* d_in, const int* in_sizes, int n_in,
                              void* d_out, int out_size) {
    const float* x       = (const float*)d_in[0];
    const float* lin_w   = (const float*)d_in[1];
    const float* lin_b   = (const float*)d_in[2];
    const float* a       = (const float*)d_in[3];
    const float* bias_kk = (const float*)d_in[4];
    const float* fc_w    = (const float*)d_in[5];
    const float* fc_b    = (const float*)d_in[6];
    float* out = (float*)d_out;

    cudaFuncSetAttribute(k2_attn, cudaFuncAttributeMaxDynamicSharedMemorySize, 218368);

    void* pL = nullptr; void* pR = nullptr;
    cudaGetSymbolAddress(&pL, g_sL);
    cudaGetSymbolAddress(&pR, g_sR);
    cudaMemsetAsync(pL, 0, 16 * 256 * sizeof(float));
    cudaMemsetAsync(pR, 0, 16 * 256 * sizeof(float));

    k1_lr<<<512, 256>>>(x, lin_w, lin_b, a);
    k2_attn<<<128, 256, 218368>>>(x, bias_kk, a);
    k3_fc<<<256, 256>>>(fc_w, fc_b, out);
}

// round 12
// speedup vs baseline: 1.0430x; 1.0430x over previous
#include <cuda_runtime.h>

// B=16, Wn=64, K=256, E=128, O=64

typedef unsigned long long ull;

__device__ __forceinline__ ull f2_add(ull a, ull b) {
    ull r; asm("add.rn.f32x2 %0,%1,%2;" : "=l"(r) : "l"(a), "l"(b)); return r;
}
__device__ __forceinline__ ull f2_fma(ull a, ull b, ull c) {
    ull r; asm("fma.rn.f32x2 %0,%1,%2,%3;" : "=l"(r) : "l"(a), "l"(b), "l"(c)); return r;
}
__device__ __forceinline__ float f2_hadd(ull a) {
    float lo, hi; asm("mov.b64 {%0,%1},%2;" : "=f"(lo), "=f"(hi) : "l"(a)); return lo + hi;
}
__device__ __forceinline__ ull f2_dup(float v) {
    ull r; asm("mov.b64 %0,{%1,%1};" : "=l"(r) : "f"(v)); return r;
}
__device__ __forceinline__ void f2_unpack(ull a, float& lo, float& hi) {
    asm("mov.b64 {%0,%1},%2;" : "=f"(lo), "=f"(hi) : "l"(a));
}

// Scratch
__device__ float g_L[16 * 256 * 128];
__device__ float g_R[16 * 256 * 128];
__device__ float g_sL[16 * 256];
__device__ float g_sR[16 * 256];
__device__ float g_h[16 * 256 * 64];

// ---------------------------------------------------------------------------
// k1: C[4096,256] = A[4096,64] x W[256,64]^T ; 4m x 4n register tiles,
// fused sL/sR row-dots (scale 0.6) via shfl + atomicAdd. grid 256, 256 thr.
// ---------------------------------------------------------------------------
__global__ void __launch_bounds__(256, 2)
k1_lr(const float* __restrict__ x, const float* __restrict__ lin_w,
      const float* __restrict__ lin_b, const float* __restrict__ a) {
    __shared__ float As[64 * 68];
    __shared__ float Ws[64 * 68];

    int bx = blockIdx.x;
    int mt = bx >> 2, nt = bx & 3;
    int b = mt >> 2, k0 = (mt & 3) * 64;
    int half = nt >> 1, e0 = (nt & 1) * 64;
    int tid = threadIdx.x;

#pragma unroll
    for (int t = 0; t < 4; t++) {
        int idx = t * 256 + tid;
        int w = idx >> 4, m4 = idx & 15;
        float4 v = *reinterpret_cast<const float4*>(x + b * 16384 + w * 256 + k0 + m4 * 4);
        *reinterpret_cast<float4*>(&As[w * 68 + m4 * 4]) = v;
    }
#pragma unroll
    for (int t = 0; t < 4; t++) {
        int idx = t * 256 + tid;
        int n = idx >> 4, w4 = idx & 15;
        float4 v = *reinterpret_cast<const float4*>(lin_w + (e0 + n) * 128 + half * 64 + w4 * 4);
        Ws[(w4 * 4 + 0) * 68 + n] = v.x;
        Ws[(w4 * 4 + 1) * 68 + n] = v.y;
        Ws[(w4 * 4 + 2) * 68 + n] = v.z;
        Ws[(w4 * 4 + 3) * 68 + n] = v.w;
    }
    __syncthreads();

    int mg = tid >> 4, ng = tid & 15;
    ull acc[4][2];
#pragma unroll
    for (int n = 0; n < 4; n++) { acc[n][0] = 0ULL; acc[n][1] = 0ULL; }

#pragma unroll 8
    for (int w = 0; w < 64; w++) {
        const ull* ap = reinterpret_cast<const ull*>(&As[w * 68 + mg * 4]);
        ull a0 = ap[0], a1 = ap[1];
        float4 wn = *reinterpret_cast<const float4*>(&Ws[w * 68 + ng * 4]);
        ull w0 = f2_dup(wn.x), w1 = f2_dup(wn.y), w2 = f2_dup(wn.z), w3 = f2_dup(wn.w);
        acc[0][0] = f2_fma(a0, w0, acc[0][0]); acc[0][1] = f2_fma(a1, w0, acc[0][1]);
        acc[1][0] = f2_fma(a0, w1, acc[1][0]); acc[1][1] = f2_fma(a1, w1, acc[1][1]);
        acc[2][0] = f2_fma(a0, w2, acc[2][0]); acc[2][1] = f2_fma(a1, w2, acc[2][1]);
        acc[3][0] = f2_fma(a0, w3, acc[3][0]); acc[3][1] = f2_fma(a1, w3, acc[3][1]);
    }

    float4 lb4 = make_float4(0.f, 0.f, 0.f, 0.f);
    if (half == 0) lb4 = *reinterpret_cast<const float4*>(lin_b + e0 + ng * 4);
    float4 a6 = *reinterpret_cast<const float4*>(a + e0 + ng * 4);
    a6.x *= 0.6f; a6.y *= 0.6f; a6.z *= 0.6f; a6.w *= 0.6f;

    float* outbase = (half ? g_R : g_L) + (b * 256 + k0 + mg * 4) * 128 + e0 + ng * 4;
    float part[4];
#pragma unroll
    for (int p = 0; p < 2; p++) {
        float lo[4], hi[4];
#pragma unroll
        for (int n = 0; n < 4; n++) f2_unpack(acc[n][p], lo[n], hi[n]);
        float l0 = lo[0] + lb4.x, l1 = lo[1] + lb4.y, l2 = lo[2] + lb4.z, l3 = lo[3] + lb4.w;
        float h0 = hi[0] + lb4.x, h1 = hi[1] + lb4.y, h2 = hi[2] + lb4.z, h3 = hi[3] + lb4.w;
        *reinterpret_cast<float4*>(outbase + (2 * p) * 128) = make_float4(l0, l1, l2, l3);
        *reinterpret_cast<float4*>(outbase + (2 * p + 1) * 128) = make_float4(h0, h1, h2, h3);
        part[2 * p]     = l0 * a6.x + l1 * a6.y + l2 * a6.z + l3 * a6.w;
        part[2 * p + 1] = h0 * a6.x + h1 * a6.y + h2 * a6.z + h3 * a6.w;
    }
#pragma unroll
    for (int o = 8; o > 0; o >>= 1) {
#pragma unroll
        for (int r = 0; r < 4; r++)
            part[r] += __shfl_down_sync(0xffffffffu, part[r], o, 16);
    }
    if (ng == 0) {
        float* sp = (half ? g_sR : g_sL) + b * 256 + k0 + mg * 4;
#pragma unroll
        for (int r = 0; r < 4; r++) atomicAdd(sp + r, part[r]);
    }
}

// ---------------------------------------------------------------------------
// k2: e = sL+sR + sum(0.4a)|L+R| + bias; softmax; h = sigmoid(p @ v).
// grid = 128 (16b x 8 itiles of 32), 256 thr.
// e-phase: 256 = 4 ig x 16 jg x 4 eh; 8i x 4j register tiles;
// 4 separate e-quarter partial buffers. smem 185,088 B.
// ---------------------------------------------------------------------------
__global__ void __launch_bounds__(256, 1)
k2_attn(const float* __restrict__ x, const float* __restrict__ bias_kk,
        const float* __restrict__ a) {
    extern __shared__ float S[];
    const int LS = 0;        // 32 x 132
    const int RS = 4224;     // 64 x 130
    const int E0 = 12544;    // 32 x 260  -> probabilities after softmax
    const int E1 = 20864;    // 32 x 260  -> xs j-half 0 after softmax
    const int E2 = 29184;    // 32 x 260  -> xs j-half 1 after softmax
    const int E3 = 37504;    // 32 x 260
    const int CS = 45824;    // 128 (0.4*a)
    const int SRS = 45952;   // 256
    const int SLS = 46208;   // 32
    const int INVS = 46240;  // 32   (total 46272 floats = 185,088 B)
    const ull ABSM = 0x7FFFFFFF7FFFFFFFULL;

    int tid = threadIdx.x;
    int b = blockIdx.x >> 3;
    int i0 = (blockIdx.x & 7) << 5;

    const float* Lg = g_L + (b * 256 + i0) * 128;
#pragma unroll
    for (int t = 0; t < 4; t++) {
        int idx = t * 256 + tid;
        int row = idx >> 5, c4 = idx & 31;
        float4 v = *reinterpret_cast<const float4*>(Lg + row * 128 + c4 * 4);
        *reinterpret_cast<float4*>(&S[LS + row * 132 + c4 * 4]) = v;
    }
    if (tid < 128) S[CS + tid] = 0.4f * a[tid];
    S[SRS + tid] = g_sR[b * 256 + tid];
    if (tid < 32) S[SLS + tid] = g_sL[b * 256 + i0 + tid];

    int eh = tid >> 6;          // e-quarter 0..3
    int r = tid & 63;
    int ig = r >> 4;            // 0..3 -> rows ig + 4u
    int jg = r & 15;            // 0..15 -> cols jt*64 + jg + 16v
    const ull* Lp[8];
#pragma unroll
    for (int u = 0; u < 8; u++)
        Lp[u] = reinterpret_cast<const ull*>(&S[LS + (ig + 4 * u) * 132]) + eh * 16;
    const ull* Cp = reinterpret_cast<const ull*>(&S[CS]) + eh * 16;
    float* Eq = &S[E0 + eh * 8320];

    // prefetch R(jt=0): 2048 float4 / 256 thr = 8 each
    const float* Rg0 = g_R + (b * 256) * 128;
    float4 pf[8];
#pragma unroll
    for (int t = 0; t < 8; t++) {
        int idx = t * 256 + tid;
        int row = idx >> 5, c4 = idx & 31;
        pf[t] = *reinterpret_cast<const float4*>(Rg0 + row * 128 + c4 * 4);
    }

    for (int jt = 0; jt < 4; jt++) {
        __syncthreads();
#pragma unroll
        for (int t = 0; t < 8; t++) {
            int idx = t * 256 + tid;
            int row = idx >> 5, c4 = idx & 31;
            float* d = &S[RS + row * 130 + c4 * 4];
            *reinterpret_cast<float2*>(d) = make_float2(pf[t].x, pf[t].y);
            *reinterpret_cast<float2*>(d + 2) = make_float2(pf[t].z, pf[t].w);
        }
        __syncthreads();

        if (jt < 3) {
            const float* Rgn = g_R + (b * 256 + (jt + 1) * 64) * 128;
#pragma unroll
            for (int t = 0; t < 8; t++) {
                int idx = t * 256 + tid;
                int row = idx >> 5, c4 = idx & 31;
                pf[t] = *reinterpret_cast<const float4*>(Rgn + row * 128 + c4 * 4);
            }
        }

        const ull* Rp0 = reinterpret_cast<const ull*>(&S[RS + (jg) * 130]) + eh * 16;
        const ull* Rp1 = reinterpret_cast<const ull*>(&S[RS + (jg + 16) * 130]) + eh * 16;
        const ull* Rp2 = reinterpret_cast<const ull*>(&S[RS + (jg + 32) * 130]) + eh * 16;
        const ull* Rp3 = reinterpret_cast<const ull*>(&S[RS + (jg + 48) * 130]) + eh * 16;

        ull acc[8][4];
#pragma unroll
        for (int u = 0; u < 8; u++)
#pragma unroll
            for (int v = 0; v < 4; v++) acc[u][v] = 0ULL;

#pragma unroll 2
        for (int ep = 0; ep < 16; ep++) {
            ull c = Cp[ep];
            ull r0 = Rp0[ep], r1 = Rp1[ep], r2 = Rp2[ep], r3 = Rp3[ep];
#pragma unroll
            for (int u = 0; u < 8; u++) {
                ull l = Lp[u][ep];
                acc[u][0] = f2_fma(f2_add(l, r0) & ABSM, c, acc[u][0]);
                acc[u][1] = f2_fma(f2_add(l, r1) & ABSM, c, acc[u][1]);
                acc[u][2] = f2_fma(f2_add(l, r2) & ABSM, c, acc[u][2]);
                acc[u][3] = f2_fma(f2_add(l, r3) & ABSM, c, acc[u][3]);
            }
        }
#pragma unroll
        for (int u = 0; u < 8; u++) {
            int i = ig + 4 * u;
#pragma unroll
            for (int v = 0; v < 4; v++) {
                int j = jt * 64 + jg + 16 * v;
                Eq[i * 260 + j] = f2_hadd(acc[u][v]);
            }
        }
    }
    __syncthreads();

    // softmax over j: 8 warps x 4 rows; fold 4 e-quarters + linear terms
    int wid = tid >> 5, lane = tid & 31;
#pragma unroll
    for (int s = 0; s < 4; s++) {
        int rr = wid * 4 + s;
        float sl = S[SLS + rr];
        const float* bp = bias_kk + (i0 + rr) * 256;
        float v[8];
        float m = -1e30f;
#pragma unroll
        for (int u = 0; u < 8; u++) {
            int c = u * 32 + lane;
            int o = rr * 260 + c;
            v[u] = S[E0 + o] + S[E1 + o] + S[E2 + o] + S[E3 + o]
                 + sl + S[SRS + c] + bp[c];
            m = fmaxf(m, v[u]);
        }
#pragma unroll
        for (int o = 16; o > 0; o >>= 1) m = fmaxf(m, __shfl_xor_sync(0xffffffffu, m, o));
        float sum = 0.f;
#pragma unroll
        for (int u = 0; u < 8; u++) {
            float p = __expf(v[u] - m);
            S[E0 + rr * 260 + u * 32 + lane] = p;
            sum += p;
        }
#pragma unroll
        for (int o = 16; o > 0; o >>= 1) sum += __shfl_xor_sync(0xffffffffu, sum, o);
        if (lane == 0) S[INVS + rr] = 1.f / sum;
    }
    __syncthreads();

    // stage x tile: j-half 0 -> E1, j-half 1 -> E2 (coalesced float4 LDG)
#pragma unroll
    for (int t = 0; t < 16; t++) {
        int idx = t * 256 + tid;
        int w2 = idx >> 6, jc4 = idx & 63;
        float4 v = *reinterpret_cast<const float4*>(x + b * 16384 + w2 * 256 + jc4 * 4);
        int base = (jc4 < 32) ? E1 : E2;
        float* d = &S[base + w2 * 130 + (jc4 & 31) * 4];
        *reinterpret_cast<float2*>(d) = make_float2(v.x, v.y);
        *reinterpret_cast<float2*>(d + 2) = make_float2(v.z, v.w);
    }
    __syncthreads();

    // h: thread = (w in 64, ih = i-quarter of 8); f[8] over full j
    int w = tid & 63;
    int ih = tid >> 6;
    ull f[8];
#pragma unroll
    for (int ii = 0; ii < 8; ii++) f[ii] = 0ULL;
    const float* pb = &S[E0 + (ih * 8) * 260];
    const ull* xq0 = reinterpret_cast<const ull*>(&S[E1 + w * 130]);
    const ull* xq1 = reinterpret_cast<const ull*>(&S[E2 + w * 130]);
    for (int j4 = 0; j4 < 32; j4++) {
        ull x0 = xq0[j4 * 2], x1 = xq0[j4 * 2 + 1];
#pragma unroll
        for (int ii = 0; ii < 8; ii++) {
            ulonglong2 pq = *reinterpret_cast<const ulonglong2*>(pb + ii * 260 + j4 * 4);
            f[ii] = f2_fma(x0, pq.x, f[ii]);
            f[ii] = f2_fma(x1, pq.y, f[ii]);
        }
    }
    for (int j4 = 0; j4 < 32; j4++) {
        ull x0 = xq1[j4 * 2], x1 = xq1[j4 * 2 + 1];
#pragma unroll
        for (int ii = 0; ii < 8; ii++) {
            ulonglong2 pq = *reinterpret_cast<const ulonglong2*>(pb + ii * 260 + 128 + j4 * 4);
            f[ii] = f2_fma(x0, pq.x, f[ii]);
            f[ii] = f2_fma(x1, pq.y, f[ii]);
        }
    }
#pragma unroll
    for (int ii = 0; ii < 8; ii++) {
        int i = ih * 8 + ii;
        float val = f2_hadd(f[ii]) * S[INVS + i];
        g_h[(b * 256 + i0 + i) * 64 + w] = 1.f / (1.f + __expf(-val));
    }
}

// ---------------------------------------------------------------------------
// k3: out[b,w,o] = sum_k h[b,k,w] fc_w[o,k] + fc_b[o]
// grid = 256 (16b x 8 wtiles x 2 ohalves), 256 thr, single staging + 1 sync
// ---------------------------------------------------------------------------
__global__ void __launch_bounds__(256, 4)
k3_fc(const float* __restrict__ fc_w, const float* __restrict__ fc_b,
      float* __restrict__ out) {
    __shared__ float T[32 * 258 + 8 * 258];
    const int FW = 0;          // 32 x 258
    const int HS = 32 * 258;   // 8 x 258

    int bx = blockIdx.x;
    int b = bx >> 4;
    int rem = bx & 15;
    int wq = rem >> 1, oh = rem & 1;
    int w0 = wq * 8, o0 = oh * 32;
    int tid = threadIdx.x;
    int w8 = tid & 7, og = tid >> 3;   // og 0..31

#pragma unroll
    for (int t = 0; t < 8; t++) {
        int idx = t * 256 + tid;
        int row = idx >> 6, c4 = idx & 63;
        float4 v = *reinterpret_cast<const float4*>(fc_w + (o0 + row) * 256 + c4 * 4);
        float* d = &T[FW + row * 258 + c4 * 4];
        *reinterpret_cast<float2*>(d) = make_float2(v.x, v.y);
        *reinterpret_cast<float2*>(d + 2) = make_float2(v.z, v.w);
    }
#pragma unroll
    for (int t = 0; t < 8; t++) {
        int idx = t * 256 + tid;
        int kk = idx >> 3, ww = idx & 7;
        T[HS + ww * 258 + kk] = g_h[(b * 256 + kk) * 64 + w0 + ww];
    }
    __syncthreads();

    const ull* hp = reinterpret_cast<const ull*>(&T[HS + w8 * 258]);
    const ull* f0 = reinterpret_cast<const ull*>(&T[FW + og * 258]);
    ull acc = 0ULL;
#pragma unroll 16
    for (int kp = 0; kp < 128; kp++)
        acc = f2_fma(hp[kp], f0[kp], acc);

    out[(b * 64 + w0 + w8) * 64 + o0 + og] = f2_hadd(acc) + fc_b[o0 + og];
}

// ---------------------------------------------------------------------------
extern "C" void kernel_launch(void* const* d_in, const int* in_sizes, int n_in,
                              void* d_out, int out_size) {
    const float* x       = (const float*)d_in[0];
    const float* lin_w   = (const float*)d_in[1];
    const float* lin_b   = (const float*)d_in[2];
    const float* a       = (const float*)d_in[3];
    const float* bias_kk = (const float*)d_in[4];
    const float* fc_w    = (const float*)d_in[5];
    const float* fc_b    = (const float*)d_in[6];
    float* out = (float*)d_out;

    cudaFuncSetAttribute(k2_attn, cudaFuncAttributeMaxDynamicSharedMemorySize, 185088);

    void* pL = nullptr; void* pR = nullptr;
    cudaGetSymbolAddress(&pL, g_sL);
    cudaGetSymbolAddress(&pR, g_sR);
    cudaMemsetAsync(pL, 0, 16 * 256 * sizeof(float));
    cudaMemsetAsync(pR, 0, 16 * 256 * sizeof(float));

    k1_lr<<<256, 256>>>(x, lin_w, lin_b, a);
    k2_attn<<<128, 256, 185088>>>(x, bias_kk, a);
    k3_fc<<<256, 256>>>(fc_w, fc_b, out);
}

// round 13
// speedup vs baseline: 1.1338x; 1.0870x over previous
#include <cuda_runtime.h>

// B=16, Wn=64, K=256, E=128, O=64

typedef unsigned long long ull;

__device__ __forceinline__ ull f2_add(ull a, ull b) {
    ull r; asm("add.rn.f32x2 %0,%1,%2;" : "=l"(r) : "l"(a), "l"(b)); return r;
}
__device__ __forceinline__ ull f2_fma(ull a, ull b, ull c) {
    ull r; asm("fma.rn.f32x2 %0,%1,%2,%3;" : "=l"(r) : "l"(a), "l"(b), "l"(c)); return r;
}
__device__ __forceinline__ float f2_hadd(ull a) {
    float lo, hi; asm("mov.b64 {%0,%1},%2;" : "=f"(lo), "=f"(hi) : "l"(a)); return lo + hi;
}
__device__ __forceinline__ ull f2_dup(float v) {
    ull r; asm("mov.b64 %0,{%1,%1};" : "=l"(r) : "f"(v)); return r;
}
__device__ __forceinline__ void f2_unpack(ull a, float& lo, float& hi) {
    asm("mov.b64 {%0,%1},%2;" : "=f"(lo), "=f"(hi) : "l"(a));
}

// Scratch
__device__ float g_L[16 * 256 * 128];
__device__ float g_R[16 * 256 * 128];
__device__ float g_sL[16 * 256];
__device__ float g_sR[16 * 256];
__device__ float g_h[16 * 256 * 64];

// ---------------------------------------------------------------------------
// k1: C[4096,256] = A[4096,64] x W[256,64]^T ; 4m x 4n register tiles,
// fused sL/sR row-dots (scale 0.6) via shfl + atomicAdd. grid 256, 256 thr.
// ---------------------------------------------------------------------------
__global__ void __launch_bounds__(256, 3)
k1_lr(const float* __restrict__ x, const float* __restrict__ lin_w,
      const float* __restrict__ lin_b, const float* __restrict__ a) {
    __shared__ float As[64 * 68];
    __shared__ float Ws[64 * 68];

    int bx = blockIdx.x;
    int mt = bx >> 2, nt = bx & 3;
    int b = mt >> 2, k0 = (mt & 3) * 64;
    int half = nt >> 1, e0 = (nt & 1) * 64;
    int tid = threadIdx.x;

#pragma unroll
    for (int t = 0; t < 4; t++) {
        int idx = t * 256 + tid;
        int w = idx >> 4, m4 = idx & 15;
        float4 v = *reinterpret_cast<const float4*>(x + b * 16384 + w * 256 + k0 + m4 * 4);
        *reinterpret_cast<float4*>(&As[w * 68 + m4 * 4]) = v;
    }
#pragma unroll
    for (int t = 0; t < 4; t++) {
        int idx = t * 256 + tid;
        int n = idx >> 4, w4 = idx & 15;
        float4 v = *reinterpret_cast<const float4*>(lin_w + (e0 + n) * 128 + half * 64 + w4 * 4);
        Ws[(w4 * 4 + 0) * 68 + n] = v.x;
        Ws[(w4 * 4 + 1) * 68 + n] = v.y;
        Ws[(w4 * 4 + 2) * 68 + n] = v.z;
        Ws[(w4 * 4 + 3) * 68 + n] = v.w;
    }
    __syncthreads();

    int mg = tid >> 4, ng = tid & 15;
    ull acc[4][2];
#pragma unroll
    for (int n = 0; n < 4; n++) { acc[n][0] = 0ULL; acc[n][1] = 0ULL; }

#pragma unroll 8
    for (int w = 0; w < 64; w++) {
        const ull* ap = reinterpret_cast<const ull*>(&As[w * 68 + mg * 4]);
        ull a0 = ap[0], a1 = ap[1];
        float4 wn = *reinterpret_cast<const float4*>(&Ws[w * 68 + ng * 4]);
        ull w0 = f2_dup(wn.x), w1 = f2_dup(wn.y), w2 = f2_dup(wn.z), w3 = f2_dup(wn.w);
        acc[0][0] = f2_fma(a0, w0, acc[0][0]); acc[0][1] = f2_fma(a1, w0, acc[0][1]);
        acc[1][0] = f2_fma(a0, w1, acc[1][0]); acc[1][1] = f2_fma(a1, w1, acc[1][1]);
        acc[2][0] = f2_fma(a0, w2, acc[2][0]); acc[2][1] = f2_fma(a1, w2, acc[2][1]);
        acc[3][0] = f2_fma(a0, w3, acc[3][0]); acc[3][1] = f2_fma(a1, w3, acc[3][1]);
    }

    float4 lb4 = make_float4(0.f, 0.f, 0.f, 0.f);
    if (half == 0) lb4 = *reinterpret_cast<const float4*>(lin_b + e0 + ng * 4);
    float4 a6 = *reinterpret_cast<const float4*>(a + e0 + ng * 4);
    a6.x *= 0.6f; a6.y *= 0.6f; a6.z *= 0.6f; a6.w *= 0.6f;

    float* outbase = (half ? g_R : g_L) + (b * 256 + k0 + mg * 4) * 128 + e0 + ng * 4;
    float part[4];
#pragma unroll
    for (int p = 0; p < 2; p++) {
        float lo[4], hi[4];
#pragma unroll
        for (int n = 0; n < 4; n++) f2_unpack(acc[n][p], lo[n], hi[n]);
        float l0 = lo[0] + lb4.x, l1 = lo[1] + lb4.y, l2 = lo[2] + lb4.z, l3 = lo[3] + lb4.w;
        float h0 = hi[0] + lb4.x, h1 = hi[1] + lb4.y, h2 = hi[2] + lb4.z, h3 = hi[3] + lb4.w;
        *reinterpret_cast<float4*>(outbase + (2 * p) * 128) = make_float4(l0, l1, l2, l3);
        *reinterpret_cast<float4*>(outbase + (2 * p + 1) * 128) = make_float4(h0, h1, h2, h3);
        part[2 * p]     = l0 * a6.x + l1 * a6.y + l2 * a6.z + l3 * a6.w;
        part[2 * p + 1] = h0 * a6.x + h1 * a6.y + h2 * a6.z + h3 * a6.w;
    }
#pragma unroll
    for (int o = 8; o > 0; o >>= 1) {
#pragma unroll
        for (int r = 0; r < 4; r++)
            part[r] += __shfl_down_sync(0xffffffffu, part[r], o, 16);
    }
    if (ng == 0) {
        float* sp = (half ? g_sR : g_sL) + b * 256 + k0 + mg * 4;
#pragma unroll
        for (int r = 0; r < 4; r++) atomicAdd(sp + r, part[r]);
    }
}

// ---------------------------------------------------------------------------
// k2: e = sL+sR + sum(0.4a)|L+R| + bias; softmax; h = sigmoid(p @ v).
// grid = 128 (16b x 8 itiles of 32), 256 thr.
// e-phase: 256 = 4 ig x 16 jg x 4 eh; 8i x 4j register tiles;
// 4 separate e-quarter partial buffers. smem 185,088 B.
// ---------------------------------------------------------------------------
__global__ void __launch_bounds__(256, 1)
k2_attn(const float* __restrict__ x, const float* __restrict__ bias_kk,
        const float* __restrict__ a) {
    extern __shared__ float S[];
    const int LS = 0;        // 32 x 132
    const int RS = 4224;     // 64 x 130
    const int E0 = 12544;    // 32 x 260  -> probabilities after softmax
    const int E1 = 20864;    // 32 x 260  -> xs j-half 0 after softmax
    const int E2 = 29184;    // 32 x 260  -> xs j-half 1 after softmax
    const int E3 = 37504;    // 32 x 260
    const int CS = 45824;    // 128 (0.4*a)
    const int SRS = 45952;   // 256
    const int SLS = 46208;   // 32
    const int INVS = 46240;  // 32   (total 46272 floats = 185,088 B)
    const ull ABSM = 0x7FFFFFFF7FFFFFFFULL;

    int tid = threadIdx.x;
    int b = blockIdx.x >> 3;
    int i0 = (blockIdx.x & 7) << 5;

    const float* Lg = g_L + (b * 256 + i0) * 128;
#pragma unroll
    for (int t = 0; t < 4; t++) {
        int idx = t * 256 + tid;
        int row = idx >> 5, c4 = idx & 31;
        float4 v = *reinterpret_cast<const float4*>(Lg + row * 128 + c4 * 4);
        *reinterpret_cast<float4*>(&S[LS + row * 132 + c4 * 4]) = v;
    }
    if (tid < 128) S[CS + tid] = 0.4f * a[tid];
    S[SRS + tid] = g_sR[b * 256 + tid];
    if (tid < 32) S[SLS + tid] = g_sL[b * 256 + i0 + tid];

    int eh = tid >> 6;          // e-quarter 0..3
    int r = tid & 63;
    int ig = r >> 4;            // 0..3 -> rows ig + 4u
    int jg = r & 15;            // 0..15 -> cols jt*64 + jg + 16v
    const ull* Lp[8];
#pragma unroll
    for (int u = 0; u < 8; u++)
        Lp[u] = reinterpret_cast<const ull*>(&S[LS + (ig + 4 * u) * 132]) + eh * 16;
    const ull* Cp = reinterpret_cast<const ull*>(&S[CS]) + eh * 16;
    float* Eq = &S[E0 + eh * 8320];

    // prefetch R(jt=0): 2048 float4 / 256 thr = 8 each
    const float* Rg0 = g_R + (b * 256) * 128;
    float4 pf[8];
#pragma unroll
    for (int t = 0; t < 8; t++) {
        int idx = t * 256 + tid;
        int row = idx >> 5, c4 = idx & 31;
        pf[t] = *reinterpret_cast<const float4*>(Rg0 + row * 128 + c4 * 4);
    }

    for (int jt = 0; jt < 4; jt++) {
        __syncthreads();
#pragma unroll
        for (int t = 0; t < 8; t++) {
            int idx = t * 256 + tid;
            int row = idx >> 5, c4 = idx & 31;
            float* d = &S[RS + row * 130 + c4 * 4];
            *reinterpret_cast<float2*>(d) = make_float2(pf[t].x, pf[t].y);
            *reinterpret_cast<float2*>(d + 2) = make_float2(pf[t].z, pf[t].w);
        }
        __syncthreads();

        if (jt < 3) {
            const float* Rgn = g_R + (b * 256 + (jt + 1) * 64) * 128;
#pragma unroll
            for (int t = 0; t < 8; t++) {
                int idx = t * 256 + tid;
                int row = idx >> 5, c4 = idx & 31;
                pf[t] = *reinterpret_cast<const float4*>(Rgn + row * 128 + c4 * 4);
            }
        }

        const ull* Rp0 = reinterpret_cast<const ull*>(&S[RS + (jg) * 130]) + eh * 16;
        const ull* Rp1 = reinterpret_cast<const ull*>(&S[RS + (jg + 16) * 130]) + eh * 16;
        const ull* Rp2 = reinterpret_cast<const ull*>(&S[RS + (jg + 32) * 130]) + eh * 16;
        const ull* Rp3 = reinterpret_cast<const ull*>(&S[RS + (jg + 48) * 130]) + eh * 16;

        ull acc[8][4];
#pragma unroll
        for (int u = 0; u < 8; u++)
#pragma unroll
            for (int v = 0; v < 4; v++) acc[u][v] = 0ULL;

#pragma unroll 2
        for (int ep = 0; ep < 16; ep++) {
            ull c = Cp[ep];
            ull r0 = Rp0[ep], r1 = Rp1[ep], r2 = Rp2[ep], r3 = Rp3[ep];
#pragma unroll
            for (int u = 0; u < 8; u++) {
                ull l = Lp[u][ep];
                acc[u][0] = f2_fma(f2_add(l, r0) & ABSM, c, acc[u][0]);
                acc[u][1] = f2_fma(f2_add(l, r1) & ABSM, c, acc[u][1]);
                acc[u][2] = f2_fma(f2_add(l, r2) & ABSM, c, acc[u][2]);
                acc[u][3] = f2_fma(f2_add(l, r3) & ABSM, c, acc[u][3]);
            }
        }
#pragma unroll
        for (int u = 0; u < 8; u++) {
            int i = ig + 4 * u;
#pragma unroll
            for (int v = 0; v < 4; v++) {
                int j = jt * 64 + jg + 16 * v;
                Eq[i * 260 + j] = f2_hadd(acc[u][v]);
            }
        }
    }
    __syncthreads();

    // softmax over j: 8 warps x 4 rows; fold 4 e-quarters + linear terms
    int wid = tid >> 5, lane = tid & 31;
#pragma unroll
    for (int s = 0; s < 4; s++) {
        int rr = wid * 4 + s;
        float sl = S[SLS + rr];
        const float* bp = bias_kk + (i0 + rr) * 256;
        float v[8];
        float m = -1e30f;
#pragma unroll
        for (int u = 0; u < 8; u++) {
            int c = u * 32 + lane;
            int o = rr * 260 + c;
            v[u] = S[E0 + o] + S[E1 + o] + S[E2 + o] + S[E3 + o]
                 + sl + S[SRS + c] + bp[c];
            m = fmaxf(m, v[u]);
        }
#pragma unroll
        for (int o = 16; o > 0; o >>= 1) m = fmaxf(m, __shfl_xor_sync(0xffffffffu, m, o));
        float sum = 0.f;
#pragma unroll
        for (int u = 0; u < 8; u++) {
            float p = __expf(v[u] - m);
            S[E0 + rr * 260 + u * 32 + lane] = p;
            sum += p;
        }
#pragma unroll
        for (int o = 16; o > 0; o >>= 1) sum += __shfl_xor_sync(0xffffffffu, sum, o);
        if (lane == 0) S[INVS + rr] = 1.f / sum;
    }
    __syncthreads();

    // stage x tile: j-half 0 -> E1, j-half 1 -> E2 (coalesced float4 LDG)
#pragma unroll
    for (int t = 0; t < 16; t++) {
        int idx = t * 256 + tid;
        int w2 = idx >> 6, jc4 = idx & 63;
        float4 v = *reinterpret_cast<const float4*>(x + b * 16384 + w2 * 256 + jc4 * 4);
        int base = (jc4 < 32) ? E1 : E2;
        float* d = &S[base + w2 * 130 + (jc4 & 31) * 4];
        *reinterpret_cast<float2*>(d) = make_float2(v.x, v.y);
        *reinterpret_cast<float2*>(d + 2) = make_float2(v.z, v.w);
    }
    __syncthreads();

    // h: thread = (w in 64, ih = i-quarter of 8); f[8] over full j
    int w = tid & 63;
    int ih = tid >> 6;
    ull f[8];
#pragma unroll
    for (int ii = 0; ii < 8; ii++) f[ii] = 0ULL;
    const float* pb = &S[E0 + (ih * 8) * 260];
    const ull* xq0 = reinterpret_cast<const ull*>(&S[E1 + w * 130]);
    const ull* xq1 = reinterpret_cast<const ull*>(&S[E2 + w * 130]);
    for (int j4 = 0; j4 < 32; j4++) {
        ull x0 = xq0[j4 * 2], x1 = xq0[j4 * 2 + 1];
#pragma unroll
        for (int ii = 0; ii < 8; ii++) {
            ulonglong2 pq = *reinterpret_cast<const ulonglong2*>(pb + ii * 260 + j4 * 4);
            f[ii] = f2_fma(x0, pq.x, f[ii]);
            f[ii] = f2_fma(x1, pq.y, f[ii]);
        }
    }
    for (int j4 = 0; j4 < 32; j4++) {
        ull x0 = xq1[j4 * 2], x1 = xq1[j4 * 2 + 1];
#pragma unroll
        for (int ii = 0; ii < 8; ii++) {
            ulonglong2 pq = *reinterpret_cast<const ulonglong2*>(pb + ii * 260 + 128 + j4 * 4);
            f[ii] = f2_fma(x0, pq.x, f[ii]);
            f[ii] = f2_fma(x1, pq.y, f[ii]);
        }
    }
#pragma unroll
    for (int ii = 0; ii < 8; ii++) {
        int i = ih * 8 + ii;
        float val = f2_hadd(f[ii]) * S[INVS + i];
        g_h[(b * 256 + i0 + i) * 64 + w] = 1.f / (1.f + __expf(-val));
    }
}

// ---------------------------------------------------------------------------
// k3: out[b,w,o] = sum_k h[b,k,w] fc_w[o,k] + fc_b[o]
// grid = 128 (16b x 8 wtiles of 8), 256 thr, single staging + 1 sync
// ---------------------------------------------------------------------------
__global__ void __launch_bounds__(256, 2)
k3_fc(const float* __restrict__ fc_w, const float* __restrict__ fc_b,
      float* __restrict__ out) {
    extern __shared__ float T[];
    const int FW = 0;       // 64 x 258
    const int HS = 16512;   // 8 x 258

    int bx = blockIdx.x;
    int b = bx >> 3, wq = bx & 7;
    int w0 = wq * 8;
    int tid = threadIdx.x;
    int w8 = tid & 7, og = tid >> 3;

#pragma unroll
    for (int t = 0; t < 16; t++) {
        int idx = t * 256 + tid;
        int row = idx >> 6, c4 = idx & 63;
        float4 v = *reinterpret_cast<const float4*>(fc_w + row * 256 + c4 * 4);
        float* d = &T[FW + row * 258 + c4 * 4];
        *reinterpret_cast<float2*>(d) = make_float2(v.x, v.y);
        *reinterpret_cast<float2*>(d + 2) = make_float2(v.z, v.w);
    }
#pragma unroll
    for (int t = 0; t < 8; t++) {
        int idx = t * 256 + tid;
        int kk = idx >> 3, ww = idx & 7;
        T[HS + ww * 258 + kk] = g_h[(b * 256 + kk) * 64 + w0 + ww];
    }
    __syncthreads();

    const ull* hp = reinterpret_cast<const ull*>(&T[HS + w8 * 258]);
    const ull* f0 = reinterpret_cast<const ull*>(&T[FW + og * 258]);
    const ull* f1 = reinterpret_cast<const ull*>(&T[FW + (og + 32) * 258]);
    ull acc0 = 0ULL, acc1 = 0ULL;
#pragma unroll 16
    for (int kp = 0; kp < 128; kp++) {
        ull h2 = hp[kp];
        acc0 = f2_fma(h2, f0[kp], acc0);
        acc1 = f2_fma(h2, f1[kp], acc1);
    }
    out[(b * 64 + w0 + w8) * 64 + og] = f2_hadd(acc0) + fc_b[og];
    out[(b * 64 + w0 + w8) * 64 + og + 32] = f2_hadd(acc1) + fc_b[og + 32];
}

// ---------------------------------------------------------------------------
extern "C" void kernel_launch(void* const* d_in, const int* in_sizes, int n_in,
                              void* d_out, int out_size) {
    const float* x       = (const float*)d_in[0];
    const float* lin_w   = (const float*)d_in[1];
    const float* lin_b   = (const float*)d_in[2];
    const float* a       = (const float*)d_in[3];
    const float* bias_kk = (const float*)d_in[4];
    const float* fc_w    = (const float*)d_in[5];
    const float* fc_b    = (const float*)d_in[6];
    float* out = (float*)d_out;

    cudaFuncSetAttribute(k2_attn, cudaFuncAttributeMaxDynamicSharedMemorySize, 185088);
    cudaFuncSetAttribute(k3_fc, cudaFuncAttributeMaxDynamicSharedMemorySize, 74304);

    void* pL = nullptr; void* pR = nullptr;
    cudaGetSymbolAddress(&pL, g_sL);
    cudaGetSymbolAddress(&pR, g_sR);
    cudaMemsetAsync(pL, 0, 16 * 256 * sizeof(float));
    cudaMemsetAsync(pR, 0, 16 * 256 * sizeof(float));

    k1_lr<<<256, 256>>>(x, lin_w, lin_b, a);
    k2_attn<<<128, 256, 185088>>>(x, bias_kk, a);
    k3_fc<<<128, 256, 74304>>>(fc_w, fc_b, out);
}

// round 14
// speedup vs baseline: 1.1903x; 1.0499x over previous
#include <cuda_runtime.h>

// B=16, Wn=64, K=256, E=128, O=64

typedef unsigned long long ull;

__device__ __forceinline__ ull f2_add(ull a, ull b) {
    ull r; asm("add.rn.f32x2 %0,%1,%2;" : "=l"(r) : "l"(a), "l"(b)); return r;
}
__device__ __forceinline__ ull f2_fma(ull a, ull b, ull c) {
    ull r; asm("fma.rn.f32x2 %0,%1,%2,%3;" : "=l"(r) : "l"(a), "l"(b), "l"(c)); return r;
}
__device__ __forceinline__ float f2_hadd(ull a) {
    float lo, hi; asm("mov.b64 {%0,%1},%2;" : "=f"(lo), "=f"(hi) : "l"(a)); return lo + hi;
}
__device__ __forceinline__ ull f2_dup(float v) {
    ull r; asm("mov.b64 %0,{%1,%1};" : "=l"(r) : "f"(v)); return r;
}
__device__ __forceinline__ void f2_unpack(ull a, float& lo, float& hi) {
    asm("mov.b64 {%0,%1},%2;" : "=f"(lo), "=f"(hi) : "l"(a));
}

// Scratch
__device__ float g_L[16 * 256 * 128];
__device__ float g_R[16 * 256 * 128];
__device__ float g_sLp[2 * 16 * 256];   // per-e-half partial row dots (no atomics)
__device__ float g_sRp[2 * 16 * 256];
__device__ float g_h[16 * 256 * 64];

// ---------------------------------------------------------------------------
// k1: C[4096,256] = A[4096,64] x W[256,64]^T ; 4m x 4n register tiles,
// fused sL/sR partial row-dots (scale 0.6) via shfl + plain store.
// grid 256, 256 thr.
// ---------------------------------------------------------------------------
__global__ void __launch_bounds__(256, 3)
k1_lr(const float* __restrict__ x, const float* __restrict__ lin_w,
      const float* __restrict__ lin_b, const float* __restrict__ a) {
    __shared__ float As[64 * 68];
    __shared__ float Ws[64 * 68];

    int bx = blockIdx.x;
    int mt = bx >> 2, nt = bx & 3;
    int b = mt >> 2, k0 = (mt & 3) * 64;
    int half = nt >> 1, e0 = (nt & 1) * 64;
    int tid = threadIdx.x;

#pragma unroll
    for (int t = 0; t < 4; t++) {
        int idx = t * 256 + tid;
        int w = idx >> 4, m4 = idx & 15;
        float4 v = *reinterpret_cast<const float4*>(x + b * 16384 + w * 256 + k0 + m4 * 4);
        *reinterpret_cast<float4*>(&As[w * 68 + m4 * 4]) = v;
    }
#pragma unroll
    for (int t = 0; t < 4; t++) {
        int idx = t * 256 + tid;
        int n = idx >> 4, w4 = idx & 15;
        float4 v = *reinterpret_cast<const float4*>(lin_w + (e0 + n) * 128 + half * 64 + w4 * 4);
        Ws[(w4 * 4 + 0) * 68 + n] = v.x;
        Ws[(w4 * 4 + 1) * 68 + n] = v.y;
        Ws[(w4 * 4 + 2) * 68 + n] = v.z;
        Ws[(w4 * 4 + 3) * 68 + n] = v.w;
    }
    __syncthreads();

    int mg = tid >> 4, ng = tid & 15;
    ull acc[4][2];
#pragma unroll
    for (int n = 0; n < 4; n++) { acc[n][0] = 0ULL; acc[n][1] = 0ULL; }

#pragma unroll 8
    for (int w = 0; w < 64; w++) {
        const ull* ap = reinterpret_cast<const ull*>(&As[w * 68 + mg * 4]);
        ull a0 = ap[0], a1 = ap[1];
        float4 wn = *reinterpret_cast<const float4*>(&Ws[w * 68 + ng * 4]);
        ull w0 = f2_dup(wn.x), w1 = f2_dup(wn.y), w2 = f2_dup(wn.z), w3 = f2_dup(wn.w);
        acc[0][0] = f2_fma(a0, w0, acc[0][0]); acc[0][1] = f2_fma(a1, w0, acc[0][1]);
        acc[1][0] = f2_fma(a0, w1, acc[1][0]); acc[1][1] = f2_fma(a1, w1, acc[1][1]);
        acc[2][0] = f2_fma(a0, w2, acc[2][0]); acc[2][1] = f2_fma(a1, w2, acc[2][1]);
        acc[3][0] = f2_fma(a0, w3, acc[3][0]); acc[3][1] = f2_fma(a1, w3, acc[3][1]);
    }

    float4 lb4 = make_float4(0.f, 0.f, 0.f, 0.f);
    if (half == 0) lb4 = *reinterpret_cast<const float4*>(lin_b + e0 + ng * 4);
    float4 a6 = *reinterpret_cast<const float4*>(a + e0 + ng * 4);
    a6.x *= 0.6f; a6.y *= 0.6f; a6.z *= 0.6f; a6.w *= 0.6f;

    float* outbase = (half ? g_R : g_L) + (b * 256 + k0 + mg * 4) * 128 + e0 + ng * 4;
    float part[4];
#pragma unroll
    for (int p = 0; p < 2; p++) {
        float lo[4], hi[4];
#pragma unroll
        for (int n = 0; n < 4; n++) f2_unpack(acc[n][p], lo[n], hi[n]);
        float l0 = lo[0] + lb4.x, l1 = lo[1] + lb4.y, l2 = lo[2] + lb4.z, l3 = lo[3] + lb4.w;
        float h0 = hi[0] + lb4.x, h1 = hi[1] + lb4.y, h2 = hi[2] + lb4.z, h3 = hi[3] + lb4.w;
        *reinterpret_cast<float4*>(outbase + (2 * p) * 128) = make_float4(l0, l1, l2, l3);
        *reinterpret_cast<float4*>(outbase + (2 * p + 1) * 128) = make_float4(h0, h1, h2, h3);
        part[2 * p]     = l0 * a6.x + l1 * a6.y + l2 * a6.z + l3 * a6.w;
        part[2 * p + 1] = h0 * a6.x + h1 * a6.y + h2 * a6.z + h3 * a6.w;
    }
#pragma unroll
    for (int o = 8; o > 0; o >>= 1) {
#pragma unroll
        for (int r = 0; r < 4; r++)
            part[r] += __shfl_down_sync(0xffffffffu, part[r], o, 16);
    }
    if (ng == 0) {
        // deterministic per-e-half slot: no atomics, no pre-zeroing needed
        float* sp = (half ? g_sRp : g_sLp) + (e0 ? 4096 : 0) + b * 256 + k0 + mg * 4;
#pragma unroll
        for (int r = 0; r < 4; r++) sp[r] = part[r];
    }
}

// ---------------------------------------------------------------------------
// k2: e = sL+sR + sum(0.4a)|L+R| + bias; softmax; h = sigmoid(p @ v).
// grid = 128 (16b x 8 itiles of 32), 256 thr.
// e-phase: 256 = 4 ig x 16 jg x 4 eh; 8i x 4j register tiles;
// 4 separate e-quarter partial buffers. smem 185,088 B.
// ---------------------------------------------------------------------------
__global__ void __launch_bounds__(256, 1)
k2_attn(const float* __restrict__ x, const float* __restrict__ bias_kk,
        const float* __restrict__ a) {
    extern __shared__ float S[];
    const int LS = 0;        // 32 x 132
    const int RS = 4224;     // 64 x 130
    const int E0 = 12544;    // 32 x 260  -> probabilities after softmax
    const int E1 = 20864;    // 32 x 260  -> xs j-half 0 after softmax
    const int E2 = 29184;    // 32 x 260  -> xs j-half 1 after softmax
    const int E3 = 37504;    // 32 x 260
    const int CS = 45824;    // 128 (0.4*a)
    const int SRS = 45952;   // 256
    const int SLS = 46208;   // 32
    const int INVS = 46240;  // 32   (total 46272 floats = 185,088 B)
    const ull ABSM = 0x7FFFFFFF7FFFFFFFULL;

    int tid = threadIdx.x;
    int b = blockIdx.x >> 3;
    int i0 = (blockIdx.x & 7) << 5;

    const float* Lg = g_L + (b * 256 + i0) * 128;
#pragma unroll
    for (int t = 0; t < 4; t++) {
        int idx = t * 256 + tid;
        int row = idx >> 5, c4 = idx & 31;
        float4 v = *reinterpret_cast<const float4*>(Lg + row * 128 + c4 * 4);
        *reinterpret_cast<float4*>(&S[LS + row * 132 + c4 * 4]) = v;
    }
    if (tid < 128) S[CS + tid] = 0.4f * a[tid];
    S[SRS + tid] = g_sRp[b * 256 + tid] + g_sRp[4096 + b * 256 + tid];
    if (tid < 32)
        S[SLS + tid] = g_sLp[b * 256 + i0 + tid] + g_sLp[4096 + b * 256 + i0 + tid];

    int eh = tid >> 6;          // e-quarter 0..3
    int r = tid & 63;
    int ig = r >> 4;            // 0..3 -> rows ig + 4u
    int jg = r & 15;            // 0..15 -> cols jt*64 + jg + 16v
    const ull* Lp[8];
#pragma unroll
    for (int u = 0; u < 8; u++)
        Lp[u] = reinterpret_cast<const ull*>(&S[LS + (ig + 4 * u) * 132]) + eh * 16;
    const ull* Cp = reinterpret_cast<const ull*>(&S[CS]) + eh * 16;
    float* Eq = &S[E0 + eh * 8320];

    // prefetch R(jt=0): 2048 float4 / 256 thr = 8 each
    const float* Rg0 = g_R + (b * 256) * 128;
    float4 pf[8];
#pragma unroll
    for (int t = 0; t < 8; t++) {
        int idx = t * 256 + tid;
        int row = idx >> 5, c4 = idx & 31;
        pf[t] = *reinterpret_cast<const float4*>(Rg0 + row * 128 + c4 * 4);
    }

    for (int jt = 0; jt < 4; jt++) {
        __syncthreads();
#pragma unroll
        for (int t = 0; t < 8; t++) {
            int idx = t * 256 + tid;
            int row = idx >> 5, c4 = idx & 31;
            float* d = &S[RS + row * 130 + c4 * 4];
            *reinterpret_cast<float2*>(d) = make_float2(pf[t].x, pf[t].y);
            *reinterpret_cast<float2*>(d + 2) = make_float2(pf[t].z, pf[t].w);
        }
        __syncthreads();

        if (jt < 3) {
            const float* Rgn = g_R + (b * 256 + (jt + 1) * 64) * 128;
#pragma unroll
            for (int t = 0; t < 8; t++) {
                int idx = t * 256 + tid;
                int row = idx >> 5, c4 = idx & 31;
                pf[t] = *reinterpret_cast<const float4*>(Rgn + row * 128 + c4 * 4);
            }
        }

        const ull* Rp0 = reinterpret_cast<const ull*>(&S[RS + (jg) * 130]) + eh * 16;
        const ull* Rp1 = reinterpret_cast<const ull*>(&S[RS + (jg + 16) * 130]) + eh * 16;
        const ull* Rp2 = reinterpret_cast<const ull*>(&S[RS + (jg + 32) * 130]) + eh * 16;
        const ull* Rp3 = reinterpret_cast<const ull*>(&S[RS + (jg + 48) * 130]) + eh * 16;

        ull acc[8][4];
#pragma unroll
        for (int u = 0; u < 8; u++)
#pragma unroll
            for (int v = 0; v < 4; v++) acc[u][v] = 0ULL;

#pragma unroll 2
        for (int ep = 0; ep < 16; ep++) {
            ull c = Cp[ep];
            ull r0 = Rp0[ep], r1 = Rp1[ep], r2 = Rp2[ep], r3 = Rp3[ep];
#pragma unroll
            for (int u = 0; u < 8; u++) {
                ull l = Lp[u][ep];
                acc[u][0] = f2_fma(f2_add(l, r0) & ABSM, c, acc[u][0]);
                acc[u][1] = f2_fma(f2_add(l, r1) & ABSM, c, acc[u][1]);
                acc[u][2] = f2_fma(f2_add(l, r2) & ABSM, c, acc[u][2]);
                acc[u][3] = f2_fma(f2_add(l, r3) & ABSM, c, acc[u][3]);
            }
        }
#pragma unroll
        for (int u = 0; u < 8; u++) {
            int i = ig + 4 * u;
#pragma unroll
            for (int v = 0; v < 4; v++) {
                int j = jt * 64 + jg + 16 * v;
                Eq[i * 260 + j] = f2_hadd(acc[u][v]);
            }
        }
    }
    __syncthreads();

    // softmax over j: 8 warps x 4 rows; fold 4 e-quarters + linear terms
    int wid = tid >> 5, lane = tid & 31;
#pragma unroll
    for (int s = 0; s < 4; s++) {
        int rr = wid * 4 + s;
        float sl = S[SLS + rr];
        const float* bp = bias_kk + (i0 + rr) * 256;
        float v[8];
        float m = -1e30f;
#pragma unroll
        for (int u = 0; u < 8; u++) {
            int c = u * 32 + lane;
            int o = rr * 260 + c;
            v[u] = S[E0 + o] + S[E1 + o] + S[E2 + o] + S[E3 + o]
                 + sl + S[SRS + c] + bp[c];
            m = fmaxf(m, v[u]);
        }
#pragma unroll
        for (int o = 16; o > 0; o >>= 1) m = fmaxf(m, __shfl_xor_sync(0xffffffffu, m, o));
        float sum = 0.f;
#pragma unroll
        for (int u = 0; u < 8; u++) {
            float p = __expf(v[u] - m);
            S[E0 + rr * 260 + u * 32 + lane] = p;
            sum += p;
        }
#pragma unroll
        for (int o = 16; o > 0; o >>= 1) sum += __shfl_xor_sync(0xffffffffu, sum, o);
        if (lane == 0) S[INVS + rr] = 1.f / sum;
    }
    __syncthreads();

    // stage x tile: j-half 0 -> E1, j-half 1 -> E2 (coalesced float4 LDG)
#pragma unroll
    for (int t = 0; t < 16; t++) {
        int idx = t * 256 + tid;
        int w2 = idx >> 6, jc4 = idx & 63;
        float4 v = *reinterpret_cast<const float4*>(x + b * 16384 + w2 * 256 + jc4 * 4);
        int base = (jc4 < 32) ? E1 : E2;
        float* d = &S[base + w2 * 130 + (jc4 & 31) * 4];
        *reinterpret_cast<float2*>(d) = make_float2(v.x, v.y);
        *reinterpret_cast<float2*>(d + 2) = make_float2(v.z, v.w);
    }
    __syncthreads();

    // h: thread = (w in 64, ih = i-quarter of 8); f[8] over full j
    int w = tid & 63;
    int ih = tid >> 6;
    ull f[8];
#pragma unroll
    for (int ii = 0; ii < 8; ii++) f[ii] = 0ULL;
    const float* pb = &S[E0 + (ih * 8) * 260];
    const ull* xq0 = reinterpret_cast<const ull*>(&S[E1 + w * 130]);
    const ull* xq1 = reinterpret_cast<const ull*>(&S[E2 + w * 130]);
    for (int j4 = 0; j4 < 32; j4++) {
        ull x0 = xq0[j4 * 2], x1 = xq0[j4 * 2 + 1];
#pragma unroll
        for (int ii = 0; ii < 8; ii++) {
            ulonglong2 pq = *reinterpret_cast<const ulonglong2*>(pb + ii * 260 + j4 * 4);
            f[ii] = f2_fma(x0, pq.x, f[ii]);
            f[ii] = f2_fma(x1, pq.y, f[ii]);
        }
    }
    for (int j4 = 0; j4 < 32; j4++) {
        ull x0 = xq1[j4 * 2], x1 = xq1[j4 * 2 + 1];
#pragma unroll
        for (int ii = 0; ii < 8; ii++) {
            ulonglong2 pq = *reinterpret_cast<const ulonglong2*>(pb + ii * 260 + 128 + j4 * 4);
            f[ii] = f2_fma(x0, pq.x, f[ii]);
            f[ii] = f2_fma(x1, pq.y, f[ii]);
        }
    }
#pragma unroll
    for (int ii = 0; ii < 8; ii++) {
        int i = ih * 8 + ii;
        float val = f2_hadd(f[ii]) * S[INVS + i];
        g_h[(b * 256 + i0 + i) * 64 + w] = 1.f / (1.f + __expf(-val));
    }
}

// ---------------------------------------------------------------------------
// k3: out[b,w,o] = sum_k h[b,k,w] fc_w[o,k] + fc_b[o]
// grid = 128 (16b x 8 wtiles of 8), 256 thr, single staging + 1 sync
// ---------------------------------------------------------------------------
__global__ void __launch_bounds__(256, 2)
k3_fc(const float* __restrict__ fc_w, const float* __restrict__ fc_b,
      float* __restrict__ out) {
    extern __shared__ float T[];
    const int FW = 0;       // 64 x 258
    const int HS = 16512;   // 8 x 258

    int bx = blockIdx.x;
    int b = bx >> 3, wq = bx & 7;
    int w0 = wq * 8;
    int tid = threadIdx.x;
    int w8 = tid & 7, og = tid >> 3;

#pragma unroll
    for (int t = 0; t < 16; t++) {
        int idx = t * 256 + tid;
        int row = idx >> 6, c4 = idx & 63;
        float4 v = *reinterpret_cast<const float4*>(fc_w + row * 256 + c4 * 4);
        float* d = &T[FW + row * 258 + c4 * 4];
        *reinterpret_cast<float2*>(d) = make_float2(v.x, v.y);
        *reinterpret_cast<float2*>(d + 2) = make_float2(v.z, v.w);
    }
#pragma unroll
    for (int t = 0; t < 8; t++) {
        int idx = t * 256 + tid;
        int kk = idx >> 3, ww = idx & 7;
        T[HS + ww * 258 + kk] = g_h[(b * 256 + kk) * 64 + w0 + ww];
    }
    __syncthreads();

    const ull* hp = reinterpret_cast<const ull*>(&T[HS + w8 * 258]);
    const ull* f0 = reinterpret_cast<const ull*>(&T[FW + og * 258]);
    const ull* f1 = reinterpret_cast<const ull*>(&T[FW + (og + 32) * 258]);
    ull acc0 = 0ULL, acc1 = 0ULL;
#pragma unroll 16
    for (int kp = 0; kp < 128; kp++) {
        ull h2 = hp[kp];
        acc0 = f2_fma(h2, f0[kp], acc0);
        acc1 = f2_fma(h2, f1[kp], acc1);
    }
    out[(b * 64 + w0 + w8) * 64 + og] = f2_hadd(acc0) + fc_b[og];
    out[(b * 64 + w0 + w8) * 64 + og + 32] = f2_hadd(acc1) + fc_b[og + 32];
}

// ---------------------------------------------------------------------------
extern "C" void kernel_launch(void* const* d_in, const int* in_sizes, int n_in,
                              void* d_out, int out_size) {
    const float* x       = (const float*)d_in[0];
    const float* lin_w   = (const float*)d_in[1];
    const float* lin_b   = (const float*)d_in[2];
    const float* a       = (const float*)d_in[3];
    const float* bias_kk = (const float*)d_in[4];
    const float* fc_w    = (const float*)d_in[5];
    const float* fc_b    = (const float*)d_in[6];
    float* out = (float*)d_out;

    cudaFuncSetAttribute(k2_attn, cudaFuncAttributeMaxDynamicSharedMemorySize, 185088);
    cudaFuncSetAttribute(k3_fc, cudaFuncAttributeMaxDynamicSharedMemorySize, 74304);

    k1_lr<<<256, 256>>>(x, lin_w, lin_b, a);
    k2_attn<<<128, 256, 185088>>>(x, bias_kk, a);
    k3_fc<<<128, 256, 74304>>>(fc_w, fc_b, out);
}

// round 15
// speedup vs baseline: 1.1977x; 1.0062x over previous
#include <cuda_runtime.h>

// B=16, Wn=64, K=256, E=128, O=64

typedef unsigned long long ull;

__device__ __forceinline__ ull f2_add(ull a, ull b) {
    ull r; asm("add.rn.f32x2 %0,%1,%2;" : "=l"(r) : "l"(a), "l"(b)); return r;
}
__device__ __forceinline__ ull f2_fma(ull a, ull b, ull c) {
    ull r; asm("fma.rn.f32x2 %0,%1,%2,%3;" : "=l"(r) : "l"(a), "l"(b), "l"(c)); return r;
}
__device__ __forceinline__ float f2_hadd(ull a) {
    float lo, hi; asm("mov.b64 {%0,%1},%2;" : "=f"(lo), "=f"(hi) : "l"(a)); return lo + hi;
}
__device__ __forceinline__ ull f2_dup(float v) {
    ull r; asm("mov.b64 %0,{%1,%1};" : "=l"(r) : "f"(v)); return r;
}
__device__ __forceinline__ void f2_unpack(ull a, float& lo, float& hi) {
    asm("mov.b64 {%0,%1},%2;" : "=f"(lo), "=f"(hi) : "l"(a));
}

// Scratch
__device__ float g_L[16 * 256 * 128];
__device__ float g_R[16 * 256 * 128];
__device__ float g_sLp[2 * 16 * 256];   // per-e-half partial row dots (no atomics)
__device__ float g_sRp[2 * 16 * 256];
__device__ float g_h[16 * 256 * 64];

// ---------------------------------------------------------------------------
// k1: C[4096,256] = A[4096,64] x W[256,64]^T ; 4m x 4n register tiles,
// fused sL/sR partial row-dots (scale 0.6) via shfl + plain store.
// grid 256, 256 thr.
// ---------------------------------------------------------------------------
__global__ void __launch_bounds__(256, 3)
k1_lr(const float* __restrict__ x, const float* __restrict__ lin_w,
      const float* __restrict__ lin_b, const float* __restrict__ a) {
    __shared__ float As[64 * 68];
    __shared__ float Ws[64 * 68];

    int bx = blockIdx.x;
    int mt = bx >> 2, nt = bx & 3;
    int b = mt >> 2, k0 = (mt & 3) * 64;
    int half = nt >> 1, e0 = (nt & 1) * 64;
    int tid = threadIdx.x;

#pragma unroll
    for (int t = 0; t < 4; t++) {
        int idx = t * 256 + tid;
        int w = idx >> 4, m4 = idx & 15;
        float4 v = *reinterpret_cast<const float4*>(x + b * 16384 + w * 256 + k0 + m4 * 4);
        *reinterpret_cast<float4*>(&As[w * 68 + m4 * 4]) = v;
    }
#pragma unroll
    for (int t = 0; t < 4; t++) {
        int idx = t * 256 + tid;
        int n = idx >> 4, w4 = idx & 15;
        float4 v = *reinterpret_cast<const float4*>(lin_w + (e0 + n) * 128 + half * 64 + w4 * 4);
        Ws[(w4 * 4 + 0) * 68 + n] = v.x;
        Ws[(w4 * 4 + 1) * 68 + n] = v.y;
        Ws[(w4 * 4 + 2) * 68 + n] = v.z;
        Ws[(w4 * 4 + 3) * 68 + n] = v.w;
    }
    __syncthreads();

    int mg = tid >> 4, ng = tid & 15;
    ull acc[4][2];
#pragma unroll
    for (int n = 0; n < 4; n++) { acc[n][0] = 0ULL; acc[n][1] = 0ULL; }

#pragma unroll 8
    for (int w = 0; w < 64; w++) {
        const ull* ap = reinterpret_cast<const ull*>(&As[w * 68 + mg * 4]);
        ull a0 = ap[0], a1 = ap[1];
        float4 wn = *reinterpret_cast<const float4*>(&Ws[w * 68 + ng * 4]);
        ull w0 = f2_dup(wn.x), w1 = f2_dup(wn.y), w2 = f2_dup(wn.z), w3 = f2_dup(wn.w);
        acc[0][0] = f2_fma(a0, w0, acc[0][0]); acc[0][1] = f2_fma(a1, w0, acc[0][1]);
        acc[1][0] = f2_fma(a0, w1, acc[1][0]); acc[1][1] = f2_fma(a1, w1, acc[1][1]);
        acc[2][0] = f2_fma(a0, w2, acc[2][0]); acc[2][1] = f2_fma(a1, w2, acc[2][1]);
        acc[3][0] = f2_fma(a0, w3, acc[3][0]); acc[3][1] = f2_fma(a1, w3, acc[3][1]);
    }

    float4 lb4 = make_float4(0.f, 0.f, 0.f, 0.f);
    if (half == 0) lb4 = *reinterpret_cast<const float4*>(lin_b + e0 + ng * 4);
    float4 a6 = *reinterpret_cast<const float4*>(a + e0 + ng * 4);
    a6.x *= 0.6f; a6.y *= 0.6f; a6.z *= 0.6f; a6.w *= 0.6f;

    float* outbase = (half ? g_R : g_L) + (b * 256 + k0 + mg * 4) * 128 + e0 + ng * 4;
    float part[4];
#pragma unroll
    for (int p = 0; p < 2; p++) {
        float lo[4], hi[4];
#pragma unroll
        for (int n = 0; n < 4; n++) f2_unpack(acc[n][p], lo[n], hi[n]);
        float l0 = lo[0] + lb4.x, l1 = lo[1] + lb4.y, l2 = lo[2] + lb4.z, l3 = lo[3] + lb4.w;
        float h0 = hi[0] + lb4.x, h1 = hi[1] + lb4.y, h2 = hi[2] + lb4.z, h3 = hi[3] + lb4.w;
        *reinterpret_cast<float4*>(outbase + (2 * p) * 128) = make_float4(l0, l1, l2, l3);
        *reinterpret_cast<float4*>(outbase + (2 * p + 1) * 128) = make_float4(h0, h1, h2, h3);
        part[2 * p]     = l0 * a6.x + l1 * a6.y + l2 * a6.z + l3 * a6.w;
        part[2 * p + 1] = h0 * a6.x + h1 * a6.y + h2 * a6.z + h3 * a6.w;
    }
#pragma unroll
    for (int o = 8; o > 0; o >>= 1) {
#pragma unroll
        for (int r = 0; r < 4; r++)
            part[r] += __shfl_down_sync(0xffffffffu, part[r], o, 16);
    }
    if (ng == 0) {
        float* sp = (half ? g_sRp : g_sLp) + (e0 ? 4096 : 0) + b * 256 + k0 + mg * 4;
#pragma unroll
        for (int r = 0; r < 4; r++) sp[r] = part[r];
    }
}

// ---------------------------------------------------------------------------
// k2: e = sL+sR + sum(0.4a)|L+R| + bias; softmax; h = sigmoid(p @ v).
// grid = 128 (16b x 8 itiles of 32), 256 thr.
// e-phase: 256 = 4 ig x 16 jg x 4 eh; 8i x 4j register tiles;
// 4 separate e-quarter partial buffers. x j-half0 staged under softmax.
// smem 185,088 B.
// ---------------------------------------------------------------------------
__global__ void __launch_bounds__(256, 1)
k2_attn(const float* __restrict__ x, const float* __restrict__ bias_kk,
        const float* __restrict__ a) {
    extern __shared__ float S[];
    const int LS = 0;        // 32 x 132
    const int RS = 4224;     // 64 x 130  (R tiles; then xs j-half 0)
    const int E0 = 12544;    // 32 x 260  -> probabilities after softmax
    const int E1 = 20864;    // 32 x 260  -> xs j-half 1 after softmax
    const int E2 = 29184;    // 32 x 260
    const int E3 = 37504;    // 32 x 260
    const int CS = 45824;    // 128 (0.4*a)
    const int SRS = 45952;   // 256
    const int SLS = 46208;   // 32
    const int INVS = 46240;  // 32   (total 46272 floats = 185,088 B)
    const ull ABSM = 0x7FFFFFFF7FFFFFFFULL;

    int tid = threadIdx.x;
    int b = blockIdx.x >> 3;
    int i0 = (blockIdx.x & 7) << 5;

    const float* Lg = g_L + (b * 256 + i0) * 128;
#pragma unroll
    for (int t = 0; t < 4; t++) {
        int idx = t * 256 + tid;
        int row = idx >> 5, c4 = idx & 31;
        float4 v = *reinterpret_cast<const float4*>(Lg + row * 128 + c4 * 4);
        *reinterpret_cast<float4*>(&S[LS + row * 132 + c4 * 4]) = v;
    }
    if (tid < 128) S[CS + tid] = 0.4f * a[tid];
    S[SRS + tid] = g_sRp[b * 256 + tid] + g_sRp[4096 + b * 256 + tid];
    if (tid < 32)
        S[SLS + tid] = g_sLp[b * 256 + i0 + tid] + g_sLp[4096 + b * 256 + i0 + tid];

    int eh = tid >> 6;          // e-quarter 0..3
    int r = tid & 63;
    int ig = r >> 4;            // 0..3 -> rows ig + 4u
    int jg = r & 15;            // 0..15 -> cols jt*64 + jg + 16v
    const ull* Lp[8];
#pragma unroll
    for (int u = 0; u < 8; u++)
        Lp[u] = reinterpret_cast<const ull*>(&S[LS + (ig + 4 * u) * 132]) + eh * 16;
    const ull* Cp = reinterpret_cast<const ull*>(&S[CS]) + eh * 16;
    float* Eq = &S[E0 + eh * 8320];

    // prefetch R(jt=0): 2048 float4 / 256 thr = 8 each
    const float* Rg0 = g_R + (b * 256) * 128;
    float4 pf[8];
#pragma unroll
    for (int t = 0; t < 8; t++) {
        int idx = t * 256 + tid;
        int row = idx >> 5, c4 = idx & 31;
        pf[t] = *reinterpret_cast<const float4*>(Rg0 + row * 128 + c4 * 4);
    }

    for (int jt = 0; jt < 4; jt++) {
        __syncthreads();
#pragma unroll
        for (int t = 0; t < 8; t++) {
            int idx = t * 256 + tid;
            int row = idx >> 5, c4 = idx & 31;
            float* d = &S[RS + row * 130 + c4 * 4];
            *reinterpret_cast<float2*>(d) = make_float2(pf[t].x, pf[t].y);
            *reinterpret_cast<float2*>(d + 2) = make_float2(pf[t].z, pf[t].w);
        }
        __syncthreads();

        if (jt < 3) {
            const float* Rgn = g_R + (b * 256 + (jt + 1) * 64) * 128;
#pragma unroll
            for (int t = 0; t < 8; t++) {
                int idx = t * 256 + tid;
                int row = idx >> 5, c4 = idx & 31;
                pf[t] = *reinterpret_cast<const float4*>(Rgn + row * 128 + c4 * 4);
            }
        }

        const ull* Rp0 = reinterpret_cast<const ull*>(&S[RS + (jg) * 130]) + eh * 16;
        const ull* Rp1 = reinterpret_cast<const ull*>(&S[RS + (jg + 16) * 130]) + eh * 16;
        const ull* Rp2 = reinterpret_cast<const ull*>(&S[RS + (jg + 32) * 130]) + eh * 16;
        const ull* Rp3 = reinterpret_cast<const ull*>(&S[RS + (jg + 48) * 130]) + eh * 16;

        ull acc[8][4];
#pragma unroll
        for (int u = 0; u < 8; u++)
#pragma unroll
            for (int v = 0; v < 4; v++) acc[u][v] = 0ULL;

#pragma unroll 2
        for (int ep = 0; ep < 16; ep++) {
            ull c = Cp[ep];
            ull r0 = Rp0[ep], r1 = Rp1[ep], r2 = Rp2[ep], r3 = Rp3[ep];
#pragma unroll
            for (int u = 0; u < 8; u++) {
                ull l = Lp[u][ep];
                acc[u][0] = f2_fma(f2_add(l, r0) & ABSM, c, acc[u][0]);
                acc[u][1] = f2_fma(f2_add(l, r1) & ABSM, c, acc[u][1]);
                acc[u][2] = f2_fma(f2_add(l, r2) & ABSM, c, acc[u][2]);
                acc[u][3] = f2_fma(f2_add(l, r3) & ABSM, c, acc[u][3]);
            }
        }
#pragma unroll
        for (int u = 0; u < 8; u++) {
            int i = ig + 4 * u;
#pragma unroll
            for (int v = 0; v < 4; v++) {
                int j = jt * 64 + jg + 16 * v;
                Eq[i * 260 + j] = f2_hadd(acc[u][v]);
            }
        }
    }
    __syncthreads();

    // Issue x j-half-0 LDGs now; their latency is hidden behind softmax.
    // (8 float4 held in registers; STS after softmax compute.)
    float4 xh0[8];
    {
        int w2 = tid >> 2, jc4 = tid & 3;  // base; each thread 8 tiles below
#pragma unroll
        for (int t = 0; t < 8; t++) {
            int idx = t * 256 + tid;
            int row = idx >> 5, c4 = idx & 31;   // row = w (0..63), c4 = j4 (0..31)
            xh0[t] = *reinterpret_cast<const float4*>(x + b * 16384 + row * 256 + c4 * 4);
        }
        (void)w2; (void)jc4;
    }

    // softmax over j: 8 warps x 4 rows; fold 4 e-quarters + linear terms
    int wid = tid >> 5, lane = tid & 31;
#pragma unroll
    for (int s = 0; s < 4; s++) {
        int rr = wid * 4 + s;
        float sl = S[SLS + rr];
        const float* bp = bias_kk + (i0 + rr) * 256;
        float v[8];
        float m = -1e30f;
#pragma unroll
        for (int u = 0; u < 8; u++) {
            int c = u * 32 + lane;
            int o = rr * 260 + c;
            v[u] = S[E0 + o] + S[E1 + o] + S[E2 + o] + S[E3 + o]
                 + sl + S[SRS + c] + bp[c];
            m = fmaxf(m, v[u]);
        }
#pragma unroll
        for (int o = 16; o > 0; o >>= 1) m = fmaxf(m, __shfl_xor_sync(0xffffffffu, m, o));
        float sum = 0.f;
#pragma unroll
        for (int u = 0; u < 8; u++) {
            float p = __expf(v[u] - m);
            S[E0 + rr * 260 + u * 32 + lane] = p;
            sum += p;
        }
#pragma unroll
        for (int o = 16; o > 0; o >>= 1) sum += __shfl_xor_sync(0xffffffffu, sum, o);
        if (lane == 0) S[INVS + rr] = 1.f / sum;
    }

    // store x j-half-0 into RS (free since e-phase ended; all warps passed
    // the post-e-phase barrier before any RS write here)
#pragma unroll
    for (int t = 0; t < 8; t++) {
        int idx = t * 256 + tid;
        int row = idx >> 5, c4 = idx & 31;
        float* d = &S[RS + row * 130 + c4 * 4];
        *reinterpret_cast<float2*>(d) = make_float2(xh0[t].x, xh0[t].y);
        *reinterpret_cast<float2*>(d + 2) = make_float2(xh0[t].z, xh0[t].w);
    }
    __syncthreads();

    // stage x j-half-1 into E1 (free after softmax; probs live in E0)
#pragma unroll
    for (int t = 0; t < 8; t++) {
        int idx = t * 256 + tid;
        int row = idx >> 5, c4 = idx & 31;
        float4 v = *reinterpret_cast<const float4*>(x + b * 16384 + row * 256 + 128 + c4 * 4);
        float* d = &S[E1 + row * 130 + c4 * 4];
        *reinterpret_cast<float2*>(d) = make_float2(v.x, v.y);
        *reinterpret_cast<float2*>(d + 2) = make_float2(v.z, v.w);
    }
    __syncthreads();

    // h: thread = (w in 64, ih = i-quarter of 8); f[8] over full j
    int w = tid & 63;
    int ih = tid >> 6;
    ull f[8];
#pragma unroll
    for (int ii = 0; ii < 8; ii++) f[ii] = 0ULL;
    const float* pb = &S[E0 + (ih * 8) * 260];
    const ull* xq0 = reinterpret_cast<const ull*>(&S[RS + w * 130]);
    const ull* xq1 = reinterpret_cast<const ull*>(&S[E1 + w * 130]);
    for (int j4 = 0; j4 < 32; j4++) {
        ull x0 = xq0[j4 * 2], x1 = xq0[j4 * 2 + 1];
#pragma unroll
        for (int ii = 0; ii < 8; ii++) {
            ulonglong2 pq = *reinterpret_cast<const ulonglong2*>(pb + ii * 260 + j4 * 4);
            f[ii] = f2_fma(x0, pq.x, f[ii]);
            f[ii] = f2_fma(x1, pq.y, f[ii]);
        }
    }
    for (int j4 = 0; j4 < 32; j4++) {
        ull x0 = xq1[j4 * 2], x1 = xq1[j4 * 2 + 1];
#pragma unroll
        for (int ii = 0; ii < 8; ii++) {
            ulonglong2 pq = *reinterpret_cast<const ulonglong2*>(pb + ii * 260 + 128 + j4 * 4);
            f[ii] = f2_fma(x0, pq.x, f[ii]);
            f[ii] = f2_fma(x1, pq.y, f[ii]);
        }
    }
#pragma unroll
    for (int ii = 0; ii < 8; ii++) {
        int i = ih * 8 + ii;
        float val = f2_hadd(f[ii]) * S[INVS + i];
        g_h[(b * 256 + i0 + i) * 64 + w] = 1.f / (1.f + __expf(-val));
    }
}

// ---------------------------------------------------------------------------
// k3: out[b,w,o] = sum_k h[b,k,w] fc_w[o,k] + fc_b[o]
// grid = 128 (16b x 8 wtiles of 8), 256 thr, single staging + 1 sync
// ---------------------------------------------------------------------------
__global__ void __launch_bounds__(256, 2)
k3_fc(const float* __restrict__ fc_w, const float* __restrict__ fc_b,
      float* __restrict__ out) {
    extern __shared__ float T[];
    const int FW = 0;       // 64 x 258
    const int HS = 16512;   // 8 x 258

    int bx = blockIdx.x;
    int b = bx >> 3, wq = bx & 7;
    int w0 = wq * 8;
    int tid = threadIdx.x;
    int w8 = tid & 7, og = tid >> 3;

    // h staging first (scalar, worst latency) so its LDGs lead the window
#pragma unroll
    for (int t = 0; t < 8; t++) {
        int idx = t * 256 + tid;
        int kk = idx >> 3, ww = idx & 7;
        T[HS + ww * 258 + kk] = g_h[(b * 256 + kk) * 64 + w0 + ww];
    }
#pragma unroll
    for (int t = 0; t < 16; t++) {
        int idx = t * 256 + tid;
        int row = idx >> 6, c4 = idx & 63;
        float4 v = *reinterpret_cast<const float4*>(fc_w + row * 256 + c4 * 4);
        float* d = &T[FW + row * 258 + c4 * 4];
        *reinterpret_cast<float2*>(d) = make_float2(v.x, v.y);
        *reinterpret_cast<float2*>(d + 2) = make_float2(v.z, v.w);
    }
    __syncthreads();

    const ull* hp = reinterpret_cast<const ull*>(&T[HS + w8 * 258]);
    const ull* f0 = reinterpret_cast<const ull*>(&T[FW + og * 258]);
    const ull* f1 = reinterpret_cast<const ull*>(&T[FW + (og + 32) * 258]);
    ull acc0 = 0ULL, acc1 = 0ULL;
#pragma unroll 16
    for (int kp = 0; kp < 128; kp++) {
        ull h2 = hp[kp];
        acc0 = f2_fma(h2, f0[kp], acc0);
        acc1 = f2_fma(h2, f1[kp], acc1);
    }
    out[(b * 64 + w0 + w8) * 64 + og] = f2_hadd(acc0) + fc_b[og];
    out[(b * 64 + w0 + w8) * 64 + og + 32] = f2_hadd(acc1) + fc_b[og + 32];
}

// ---------------------------------------------------------------------------
extern "C" void kernel_launch(void* const* d_in, const int* in_sizes, int n_in,
                              void* d_out, int out_size) {
    const float* x       = (const float*)d_in[0];
    const float* lin_w   = (const float*)d_in[1];
    const float* lin_b   = (const float*)d_in[2];
    const float* a       = (const float*)d_in[3];
    const float* bias_kk = (const float*)d_in[4];
    const float* fc_w    = (const float*)d_in[5];
    const float* fc_b    = (const float*)d_in[6];
    float* out = (float*)d_out;

    cudaFuncSetAttribute(k2_attn, cudaFuncAttributeMaxDynamicSharedMemorySize, 185088);
    cudaFuncSetAttribute(k3_fc, cudaFuncAttributeMaxDynamicSharedMemorySize, 74304);

    k1_lr<<<256, 256>>>(x, lin_w, lin_b, a);
    k2_attn<<<128, 256, 185088>>>(x, bias_kk, a);
    k3_fc<<<128, 256, 74304>>>(fc_w, fc_b, out);
}